// round 1
// baseline (speedup 1.0000x reference)
#include <cuda_runtime.h>
#include <cstdint>

// Problem constants
#define V_SIZE   30522
#define HDIM     768
#define BATCH    64
#define SEQ      512
#define NEW_ROWS 10004
#define N_NODES  10002
#define N_SOFT   8
#define N_EDGES  50000
#define LEAKY    0.2f

// ---------------- scratch (static device arrays; no allocations) ----------------
__device__ __align__(128) float g_h[N_NODES * HDIM];    // h = feat @ W_gat
__device__ __align__(128) float g_ne[N_NODES * HDIM];   // feat + agg  (final new-row embeddings)
__device__ float g_ssrc[N_NODES];
__device__ float g_sdst[N_NODES];
__device__ int   g_cnt[N_NODES];
__device__ int   g_rowstart[N_NODES + 1];
__device__ int   g_cursor[N_NODES];
__device__ int   g_esrc[N_EDGES];
__device__ int   g_x64;   // 1 if x buffer is int64, else int32
__device__ int   g_e64;   // 1 if edge_index buffer is int64, else int32

// ---------------- helpers ----------------
__device__ __forceinline__ long long ldidx(const void* p, long long i, int is64) {
    if (is64) return ((const long long*)p)[i];
    return (long long)(((const int*)p)[i]);
}

__device__ __forceinline__ unsigned f2tf32(float f) {
    unsigned r;
    asm("cvt.rna.tf32.f32 %0, %1;" : "=r"(r) : "f"(f));
    return r;
}

// ---------------- dtype detection (int32 vs int64 index buffers) ----------------
__global__ void k_detect(const unsigned* x, const unsigned* ei) {
    if (threadIdx.x == 0 && blockIdx.x == 0) {
        unsigned a = 0, b = 0;
        #pragma unroll
        for (int i = 0; i < 8; i++) { a |= x[2 * i + 1]; b |= ei[2 * i + 1]; }
        g_x64 = (a == 0) ? 1 : 0;
        g_e64 = (b == 0) ? 1 : 0;
    }
}

// ---------------- zero histogram ----------------
__global__ void k_zero() {
    int i = blockIdx.x * blockDim.x + threadIdx.x;
    if (i < N_NODES) g_cnt[i] = 0;
}

// ---------------- GEMM: g_h[10002,768] = A[10002,768] * W[768,768], TF32 MMA ----------------
// A = new_weight rows 1..10002
#define BM 128
#define BN 128
#define BKK 32
#define AS_STRIDE 36    // floats; bank = (4*row + col) % 32 -> conflict-free frags
#define BS_STRIDE 136   // floats; bank = (8*k + n) % 32 -> conflict-free frags

__global__ __launch_bounds__(256) void k_gemm(const float* __restrict__ Aw,
                                              const float* __restrict__ W) {
    __shared__ float As[BM * AS_STRIDE];
    __shared__ float Bs[BKK * BS_STRIDE];

    const int tid  = threadIdx.x;
    const int warp = tid >> 5, lane = tid & 31;
    const int wm = warp >> 1, wn = warp & 1;       // warp grid 4 (M) x 2 (N)
    const int g = lane >> 2, t = lane & 3;
    const int m0 = blockIdx.x * BM;
    const int n0 = blockIdx.y * BN;

    float c[2][8][4];
    #pragma unroll
    for (int mm = 0; mm < 2; mm++)
        #pragma unroll
        for (int nn = 0; nn < 8; nn++)
            #pragma unroll
            for (int q = 0; q < 4; q++) c[mm][nn][q] = 0.0f;

    for (int kt = 0; kt < HDIM; kt += BKK) {
        // Load A tile (rows m0..m0+127, cols kt..kt+31), tf32-convert
        #pragma unroll
        for (int i = 0; i < 4; i++) {
            int idx = tid + i * 256;          // 0..1023
            int r = idx >> 3;
            int c4 = (idx & 7) * 4;
            float4 v = make_float4(0.f, 0.f, 0.f, 0.f);
            int grow = m0 + r;
            if (grow < N_NODES) v = *(const float4*)(Aw + (long long)grow * HDIM + kt + c4);
            v.x = __uint_as_float(f2tf32(v.x));
            v.y = __uint_as_float(f2tf32(v.y));
            v.z = __uint_as_float(f2tf32(v.z));
            v.w = __uint_as_float(f2tf32(v.w));
            *(float4*)(As + r * AS_STRIDE + c4) = v;
        }
        // Load B tile (W rows kt..kt+31, cols n0..n0+127), tf32-convert
        #pragma unroll
        for (int i = 0; i < 4; i++) {
            int idx = tid + i * 256;
            int k = idx >> 5;
            int n4 = (idx & 31) * 4;
            float4 v = *(const float4*)(W + (long long)(kt + k) * HDIM + n0 + n4);
            v.x = __uint_as_float(f2tf32(v.x));
            v.y = __uint_as_float(f2tf32(v.y));
            v.z = __uint_as_float(f2tf32(v.z));
            v.w = __uint_as_float(f2tf32(v.w));
            *(float4*)(Bs + k * BS_STRIDE + n4) = v;
        }
        __syncthreads();

        #pragma unroll
        for (int ks = 0; ks < 4; ks++) {
            const int kb = ks * 8;
            unsigned a[2][4], b2[8][2];
            #pragma unroll
            for (int mm = 0; mm < 2; mm++) {
                int rb = wm * 32 + mm * 16;
                a[mm][0] = __float_as_uint(As[(rb + g) * AS_STRIDE + kb + t]);
                a[mm][1] = __float_as_uint(As[(rb + 8 + g) * AS_STRIDE + kb + t]);
                a[mm][2] = __float_as_uint(As[(rb + g) * AS_STRIDE + kb + t + 4]);
                a[mm][3] = __float_as_uint(As[(rb + 8 + g) * AS_STRIDE + kb + t + 4]);
            }
            #pragma unroll
            for (int nn = 0; nn < 8; nn++) {
                int col = wn * 64 + nn * 8 + g;
                b2[nn][0] = __float_as_uint(Bs[(kb + t) * BS_STRIDE + col]);
                b2[nn][1] = __float_as_uint(Bs[(kb + t + 4) * BS_STRIDE + col]);
            }
            #pragma unroll
            for (int mm = 0; mm < 2; mm++)
                #pragma unroll
                for (int nn = 0; nn < 8; nn++) {
                    asm volatile(
                        "mma.sync.aligned.m16n8k8.row.col.f32.tf32.tf32.f32 "
                        "{%0,%1,%2,%3},{%4,%5,%6,%7},{%8,%9},{%0,%1,%2,%3};"
                        : "+f"(c[mm][nn][0]), "+f"(c[mm][nn][1]),
                          "+f"(c[mm][nn][2]), "+f"(c[mm][nn][3])
                        : "r"(a[mm][0]), "r"(a[mm][1]), "r"(a[mm][2]), "r"(a[mm][3]),
                          "r"(b2[nn][0]), "r"(b2[nn][1]));
                }
        }
        __syncthreads();
    }

    // Epilogue: store h
    #pragma unroll
    for (int mm = 0; mm < 2; mm++) {
        int row = m0 + wm * 32 + mm * 16 + g;
        #pragma unroll
        for (int nn = 0; nn < 8; nn++) {
            int col = n0 + wn * 64 + nn * 8 + t * 2;
            if (row < N_NODES) {
                float2 v0 = make_float2(c[mm][nn][0], c[mm][nn][1]);
                *(float2*)(g_h + (long long)row * HDIM + col) = v0;
            }
            if (row + 8 < N_NODES) {
                float2 v1 = make_float2(c[mm][nn][2], c[mm][nn][3]);
                *(float2*)(g_h + (long long)(row + 8) * HDIM + col) = v1;
            }
        }
    }
}

// ---------------- attention score projections: s_src = h . a_src, s_dst = h . a_dst ----------------
__global__ void k_sdots(const float* __restrict__ a_src, const float* __restrict__ a_dst) {
    int w = (blockIdx.x * blockDim.x + threadIdx.x) >> 5;
    int lane = threadIdx.x & 31;
    if (w >= N_NODES) return;
    const float* hr = g_h + (long long)w * HDIM;
    float s1 = 0.f, s2 = 0.f;
    #pragma unroll
    for (int cidx = 0; cidx < HDIM / 32; cidx++) {
        int col = lane + 32 * cidx;
        float v = hr[col];
        s1 += v * a_src[col];
        s2 += v * a_dst[col];
    }
    #pragma unroll
    for (int o = 16; o; o >>= 1) {
        s1 += __shfl_xor_sync(0xffffffffu, s1, o);
        s2 += __shfl_xor_sync(0xffffffffu, s2, o);
    }
    if (lane == 0) { g_ssrc[w] = s1; g_sdst[w] = s2; }
}

// ---------------- CSR build: histogram -> scan -> scatter ----------------
__global__ void k_hist(const void* ei) {
    int e = blockIdx.x * blockDim.x + threadIdx.x;
    if (e < N_EDGES) {
        int dst = (int)ldidx(ei, (long long)N_EDGES + e, g_e64);
        atomicAdd(&g_cnt[dst], 1);
    }
}

__global__ void k_scan() {
    __shared__ int sm[1024];
    __shared__ int s_carry;
    int tid = threadIdx.x;
    if (tid == 0) s_carry = 0;
    __syncthreads();
    for (int base = 0; base < N_NODES; base += 1024) {
        int i = base + tid;
        int v = (i < N_NODES) ? g_cnt[i] : 0;
        sm[tid] = v;
        __syncthreads();
        for (int off = 1; off < 1024; off <<= 1) {
            int tv = (tid >= off) ? sm[tid - off] : 0;
            __syncthreads();
            sm[tid] += tv;
            __syncthreads();
        }
        int carry = s_carry;
        int excl = carry + sm[tid] - v;
        if (i < N_NODES) { g_rowstart[i] = excl; g_cursor[i] = excl; }
        __syncthreads();
        if (tid == 1023) s_carry = carry + sm[1023];
        __syncthreads();
    }
    if (tid == 0) g_rowstart[N_NODES] = s_carry;
}

__global__ void k_scatter(const void* ei) {
    int e = blockIdx.x * blockDim.x + threadIdx.x;
    if (e < N_EDGES) {
        int src = (int)ldidx(ei, e, g_e64);
        int dst = (int)ldidx(ei, (long long)N_EDGES + e, g_e64);
        int pos = atomicAdd(&g_cursor[dst], 1);
        g_esrc[pos] = src;
    }
}

// ---------------- per-dst softmax + aggregate (pull), write feat + agg ----------------
__global__ void k_gat(const float* __restrict__ new_weight) {
    int w = (blockIdx.x * blockDim.x + threadIdx.x) >> 5;
    int lane = threadIdx.x & 31;
    if (w >= N_NODES) return;

    int start = g_rowstart[w];
    int end   = g_rowstart[w + 1];
    float sd = g_sdst[w];

    // pass 1: max
    float m = -INFINITY;
    for (int i = start + lane; i < end; i += 32) {
        float e = g_ssrc[g_esrc[i]] + sd;
        e = (e >= 0.f) ? e : LEAKY * e;
        m = fmaxf(m, e);
    }
    #pragma unroll
    for (int o = 16; o; o >>= 1) m = fmaxf(m, __shfl_xor_sync(0xffffffffu, m, o));

    // pass 2: denom
    float den = 0.f;
    if (end > start) {
        for (int i = start + lane; i < end; i += 32) {
            float e = g_ssrc[g_esrc[i]] + sd;
            e = (e >= 0.f) ? e : LEAKY * e;
            den += expf(e - m);
        }
        #pragma unroll
        for (int o = 16; o; o >>= 1) den += __shfl_xor_sync(0xffffffffu, den, o);
    }

    // pass 3: aggregate (sequential over the segment; all lanes cooperate on columns)
    float acc[HDIM / 32];
    #pragma unroll
    for (int cidx = 0; cidx < HDIM / 32; cidx++) acc[cidx] = 0.f;

    float inv = 1.0f / (den + 1e-16f);
    for (int i = start; i < end; i++) {
        int s = g_esrc[i];
        float e = g_ssrc[s] + sd;
        e = (e >= 0.f) ? e : LEAKY * e;
        float al = expf(e - m) * inv;
        const float* hr = g_h + (long long)s * HDIM;
        #pragma unroll
        for (int cidx = 0; cidx < HDIM / 32; cidx++)
            acc[cidx] += al * hr[lane + 32 * cidx];
    }

    const float* fr = new_weight + (long long)(1 + w) * HDIM;  // feat row
    float* outr = g_ne + (long long)w * HDIM;
    #pragma unroll
    for (int cidx = 0; cidx < HDIM / 32; cidx++) {
        int col = lane + 32 * cidx;
        outr[col] = fr[col] + acc[cidx];
    }
}

// ---------------- final gather: soft prompt + embedding lookup ----------------
__global__ void k_gather(const void* __restrict__ x,
                         const float* __restrict__ ow,
                         const float* __restrict__ nw,
                         const float* __restrict__ soft,
                         float* __restrict__ out) {
    int w = (blockIdx.x * blockDim.x + threadIdx.x) >> 5;  // token index
    int lane = threadIdx.x & 31;
    if (w >= BATCH * SEQ) return;
    int b = w / SEQ, s = w % SEQ;

    const float* srcrow;
    if (s < N_SOFT) {
        srcrow = soft + (long long)s * HDIM;
    } else {
        long long idx = ldidx(x, (long long)b * SEQ + s, g_x64);
        if (idx < V_SIZE)                 srcrow = ow + idx * HDIM;
        else if (idx < V_SIZE + N_NODES)  srcrow = g_ne + (idx - V_SIZE) * HDIM;
        else                              srcrow = nw + (long long)(NEW_ROWS - 1) * HDIM;
    }
    const float4* s4 = (const float4*)srcrow;
    float4* o4 = (float4*)(out + (long long)w * HDIM);
    #pragma unroll
    for (int j = 0; j < HDIM / 128; j++)  // 6 float4 per lane
        o4[lane + 32 * j] = s4[lane + 32 * j];
}

// ---------------- launch ----------------
extern "C" void kernel_launch(void* const* d_in, const int* in_sizes, int n_in,
                              void* d_out, int out_size) {
    const void*  x    = d_in[0];
    const void*  ei   = d_in[1];
    const float* ow   = (const float*)d_in[2];
    const float* nw   = (const float*)d_in[3];
    const float* soft = (const float*)d_in[4];
    const float* Wg   = (const float*)d_in[5];
    const float* asrc = (const float*)d_in[6];
    const float* adst = (const float*)d_in[7];
    float* out = (float*)d_out;

    k_detect<<<1, 32>>>((const unsigned*)x, (const unsigned*)ei);
    k_zero<<<(N_NODES + 1023) / 1024, 1024>>>();

    dim3 ggrid((N_NODES + BM - 1) / BM, HDIM / BN);
    k_gemm<<<ggrid, 256>>>(nw + HDIM, Wg);   // A = new_weight rows 1..10002

    k_sdots<<<(N_NODES * 32 + 255) / 256, 256>>>(asrc, adst);

    k_hist<<<(N_EDGES + 1023) / 1024, 1024>>>(ei);
    k_scan<<<1, 1024>>>();
    k_scatter<<<(N_EDGES + 1023) / 1024, 1024>>>(ei);

    k_gat<<<(N_NODES * 32 + 255) / 256, 256>>>(nw);

    k_gather<<<(BATCH * SEQ * 32 + 255) / 256, 256>>>(x, ow, nw, soft, out);
}

// round 2
// speedup vs baseline: 1.1032x; 1.1032x over previous
#include <cuda_runtime.h>
#include <cstdint>

// Problem constants
#define V_SIZE   30522
#define HDIM     768
#define BATCH    64
#define SEQ      512
#define NEW_ROWS 10004
#define N_NODES  10002
#define N_SOFT   8
#define N_EDGES  50000
#define LEAKY    0.2f

// ---------------- scratch (static device arrays; no allocations) ----------------
__device__ __align__(128) float g_h[N_NODES * HDIM];    // h = feat @ W_gat
__device__ __align__(128) float g_ne[N_NODES * HDIM];   // feat + agg
__device__ float g_ssrc[N_NODES];
__device__ float g_sdst[N_NODES];
__device__ int   g_cnt[N_NODES];
__device__ int   g_rowstart[N_NODES + 1];
__device__ int   g_cursor[N_NODES];
__device__ int   g_esrc[N_EDGES];
__device__ int   g_x64;
__device__ int   g_e64;

// ---------------- helpers ----------------
__device__ __forceinline__ long long ldidx(const void* p, long long i, int is64) {
    if (is64) return ((const long long*)p)[i];
    return (long long)(((const int*)p)[i]);
}

__device__ __forceinline__ unsigned f2tf32(float f) {
    unsigned r;
    asm("cvt.rna.tf32.f32 %0, %1;" : "=r"(r) : "f"(f));
    return r;
}

__device__ __forceinline__ void cpa16(uint32_t saddr, const void* gaddr, bool pred) {
    if (pred)
        asm volatile("cp.async.cg.shared.global [%0], [%1], 16;\n" :: "r"(saddr), "l"(gaddr));
    else
        asm volatile("cp.async.cg.shared.global [%0], [%1], 16, 0;\n" :: "r"(saddr), "l"(gaddr));
}

// ---------------- init: zero counters/score arrays + dtype detect ----------------
__global__ void k_init(const unsigned* x, const unsigned* ei) {
    int i = blockIdx.x * blockDim.x + threadIdx.x;
    if (i < N_NODES) { g_cnt[i] = 0; g_ssrc[i] = 0.f; g_sdst[i] = 0.f; }
    if (i == 0) {
        unsigned a = 0, b = 0;
        #pragma unroll
        for (int j = 0; j < 8; j++) { a |= x[2 * j + 1]; b |= ei[2 * j + 1]; }
        g_x64 = (a == 0) ? 1 : 0;
        g_e64 = (b == 0) ? 1 : 0;
    }
}

// ---------------- GEMM: g_h = A[10002,768] * W[768,768], TF32 MMA, 2-stage cp.async ----------------
#define BM 128
#define BN 128
#define BKK 32
#define AS_STRIDE 36
#define BS_STRIDE 136
#define STAGE_FLOATS (BM * AS_STRIDE + BKK * BS_STRIDE)
#define GEMM_SMEM_BYTES (2 * STAGE_FLOATS * 4)

extern __shared__ float dynsmem[];

__global__ __launch_bounds__(256) void k_gemm(const float* __restrict__ Aw,
                                              const float* __restrict__ W,
                                              const float* __restrict__ asrc,
                                              const float* __restrict__ adst) {
    const int tid  = threadIdx.x;
    const int warp = tid >> 5, lane = tid & 31;
    const int wm = warp >> 1, wn = warp & 1;       // warp grid 4 (M) x 2 (N)
    const int g = lane >> 2, t = lane & 3;
    const int m0 = blockIdx.x * BM;
    const int n0 = blockIdx.y * BN;

    float c[2][8][4];
    #pragma unroll
    for (int mm = 0; mm < 2; mm++)
        #pragma unroll
        for (int nn = 0; nn < 8; nn++)
            #pragma unroll
            for (int q = 0; q < 4; q++) c[mm][nn][q] = 0.0f;

    // per-thread load coordinates (4 chunks of 16B for A, 4 for B)
    const int NT = HDIM / BKK;   // 24

    auto load_tile = [&](int kt, int stage) {
        float* As = dynsmem + stage * STAGE_FLOATS;
        float* Bs = As + BM * AS_STRIDE;
        #pragma unroll
        for (int i = 0; i < 4; i++) {
            int idx = tid + i * 256;
            // A chunk
            int r  = idx >> 3;
            int c4 = (idx & 7) * 4;
            int grow = m0 + r;
            bool ok = grow < N_NODES;
            const float* gp = Aw + (long long)(ok ? grow : 0) * HDIM + kt + c4;
            uint32_t sa = (uint32_t)__cvta_generic_to_shared(As + r * AS_STRIDE + c4);
            cpa16(sa, gp, ok);
            // B chunk
            int k  = idx >> 5;
            int n4 = (idx & 31) * 4;
            const float* gq = W + (long long)(kt + k) * HDIM + n0 + n4;
            uint32_t sb = (uint32_t)__cvta_generic_to_shared(Bs + k * BS_STRIDE + n4);
            cpa16(sb, gq, true);
        }
    };

    load_tile(0, 0);
    asm volatile("cp.async.commit_group;\n");

    for (int kt = 0; kt < NT; kt++) {
        if (kt + 1 < NT) {
            load_tile((kt + 1) * BKK, (kt + 1) & 1);
            asm volatile("cp.async.commit_group;\n");
            asm volatile("cp.async.wait_group 1;\n");
        } else {
            asm volatile("cp.async.wait_group 0;\n");
        }
        __syncthreads();

        const float* As = dynsmem + (kt & 1) * STAGE_FLOATS;
        const float* Bs = As + BM * AS_STRIDE;

        #pragma unroll
        for (int ks = 0; ks < 4; ks++) {
            const int kb = ks * 8;
            unsigned a[2][4], b2[8][2];
            #pragma unroll
            for (int mm = 0; mm < 2; mm++) {
                int rb = wm * 32 + mm * 16;
                a[mm][0] = f2tf32(As[(rb + g) * AS_STRIDE + kb + t]);
                a[mm][1] = f2tf32(As[(rb + 8 + g) * AS_STRIDE + kb + t]);
                a[mm][2] = f2tf32(As[(rb + g) * AS_STRIDE + kb + t + 4]);
                a[mm][3] = f2tf32(As[(rb + 8 + g) * AS_STRIDE + kb + t + 4]);
            }
            #pragma unroll
            for (int nn = 0; nn < 8; nn++) {
                int col = wn * 64 + nn * 8 + g;
                b2[nn][0] = f2tf32(Bs[(kb + t) * BS_STRIDE + col]);
                b2[nn][1] = f2tf32(Bs[(kb + t + 4) * BS_STRIDE + col]);
            }
            #pragma unroll
            for (int mm = 0; mm < 2; mm++)
                #pragma unroll
                for (int nn = 0; nn < 8; nn++) {
                    asm volatile(
                        "mma.sync.aligned.m16n8k8.row.col.f32.tf32.tf32.f32 "
                        "{%0,%1,%2,%3},{%4,%5,%6,%7},{%8,%9},{%0,%1,%2,%3};"
                        : "+f"(c[mm][nn][0]), "+f"(c[mm][nn][1]),
                          "+f"(c[mm][nn][2]), "+f"(c[mm][nn][3])
                        : "r"(a[mm][0]), "r"(a[mm][1]), "r"(a[mm][2]), "r"(a[mm][3]),
                          "r"(b2[nn][0]), "r"(b2[nn][1]));
                }
        }
        __syncthreads();
    }

    // Epilogue: store h + fused partial dots with a_src/a_dst
    #pragma unroll
    for (int mm = 0; mm < 2; mm++) {
        int row = m0 + wm * 32 + mm * 16 + g;
        float s1a = 0.f, s1b = 0.f, s2a = 0.f, s2b = 0.f;
        #pragma unroll
        for (int nn = 0; nn < 8; nn++) {
            int col = n0 + wn * 64 + nn * 8 + t * 2;
            float w0s = asrc[col], w1s = asrc[col + 1];
            float w0d = adst[col], w1d = adst[col + 1];
            s1a += c[mm][nn][0] * w0s + c[mm][nn][1] * w1s;
            s2a += c[mm][nn][0] * w0d + c[mm][nn][1] * w1d;
            s1b += c[mm][nn][2] * w0s + c[mm][nn][3] * w1s;
            s2b += c[mm][nn][2] * w0d + c[mm][nn][3] * w1d;
            if (row < N_NODES) {
                float2 v0 = make_float2(c[mm][nn][0], c[mm][nn][1]);
                *(float2*)(g_h + (long long)row * HDIM + col) = v0;
            }
            if (row + 8 < N_NODES) {
                float2 v1 = make_float2(c[mm][nn][2], c[mm][nn][3]);
                *(float2*)(g_h + (long long)(row + 8) * HDIM + col) = v1;
            }
        }
        // reduce over the 4 lanes (t=0..3) sharing each row
        #pragma unroll
        for (int off = 1; off < 4; off <<= 1) {
            s1a += __shfl_xor_sync(0xffffffffu, s1a, off);
            s2a += __shfl_xor_sync(0xffffffffu, s2a, off);
            s1b += __shfl_xor_sync(0xffffffffu, s1b, off);
            s2b += __shfl_xor_sync(0xffffffffu, s2b, off);
        }
        if (t == 0) {
            if (row < N_NODES) {
                atomicAdd(&g_ssrc[row], s1a);
                atomicAdd(&g_sdst[row], s2a);
            }
            if (row + 8 < N_NODES) {
                atomicAdd(&g_ssrc[row + 8], s1b);
                atomicAdd(&g_sdst[row + 8], s2b);
            }
        }
    }
}

// ---------------- CSR build: histogram -> scan -> scatter ----------------
__global__ void k_hist(const void* ei) {
    int e = blockIdx.x * blockDim.x + threadIdx.x;
    if (e < N_EDGES) {
        int dst = (int)ldidx(ei, (long long)N_EDGES + e, g_e64);
        atomicAdd(&g_cnt[dst], 1);
    }
}

__global__ __launch_bounds__(1024) void k_scan() {
    __shared__ int wsum[32];
    __shared__ int s_carry;
    int tid = threadIdx.x;
    int lane = tid & 31, warp = tid >> 5;
    if (tid == 0) s_carry = 0;
    __syncthreads();
    for (int base = 0; base < N_NODES; base += 1024) {
        int i = base + tid;
        int v = (i < N_NODES) ? g_cnt[i] : 0;
        // inclusive warp scan
        int s = v;
        #pragma unroll
        for (int off = 1; off < 32; off <<= 1) {
            int tv = __shfl_up_sync(0xffffffffu, s, off);
            if (lane >= off) s += tv;
        }
        if (lane == 31) wsum[warp] = s;
        __syncthreads();
        if (warp == 0) {
            int w = wsum[lane];
            #pragma unroll
            for (int off = 1; off < 32; off <<= 1) {
                int tv = __shfl_up_sync(0xffffffffu, w, off);
                if (lane >= off) w += tv;
            }
            wsum[lane] = w;
        }
        __syncthreads();
        int carry = s_carry;
        int woff = (warp > 0) ? wsum[warp - 1] : 0;
        int excl = carry + woff + s - v;
        if (i < N_NODES) { g_rowstart[i] = excl; g_cursor[i] = excl; }
        __syncthreads();
        if (tid == 0) s_carry = carry + wsum[31];
        __syncthreads();
    }
    if (tid == 0) g_rowstart[N_NODES] = s_carry;
}

__global__ void k_scatter(const void* ei) {
    int e = blockIdx.x * blockDim.x + threadIdx.x;
    if (e < N_EDGES) {
        int src = (int)ldidx(ei, e, g_e64);
        int dst = (int)ldidx(ei, (long long)N_EDGES + e, g_e64);
        int pos = atomicAdd(&g_cursor[dst], 1);
        g_esrc[pos] = src;
    }
}

// ---------------- per-dst softmax + aggregate (pull), write feat + agg ----------------
__global__ void k_gat(const float* __restrict__ new_weight) {
    int w = (blockIdx.x * blockDim.x + threadIdx.x) >> 5;
    int lane = threadIdx.x & 31;
    if (w >= N_NODES) return;

    int start = g_rowstart[w];
    int end   = g_rowstart[w + 1];
    float sd = g_sdst[w];

    float m = -INFINITY;
    for (int i = start + lane; i < end; i += 32) {
        float e = g_ssrc[g_esrc[i]] + sd;
        e = (e >= 0.f) ? e : LEAKY * e;
        m = fmaxf(m, e);
    }
    #pragma unroll
    for (int o = 16; o; o >>= 1) m = fmaxf(m, __shfl_xor_sync(0xffffffffu, m, o));

    float den = 0.f;
    if (end > start) {
        for (int i = start + lane; i < end; i += 32) {
            float e = g_ssrc[g_esrc[i]] + sd;
            e = (e >= 0.f) ? e : LEAKY * e;
            den += expf(e - m);
        }
        #pragma unroll
        for (int o = 16; o; o >>= 1) den += __shfl_xor_sync(0xffffffffu, den, o);
    }

    float acc[HDIM / 32];
    #pragma unroll
    for (int cidx = 0; cidx < HDIM / 32; cidx++) acc[cidx] = 0.f;

    float inv = 1.0f / (den + 1e-16f);
    for (int i = start; i < end; i++) {
        int s = g_esrc[i];
        float e = g_ssrc[s] + sd;
        e = (e >= 0.f) ? e : LEAKY * e;
        float al = expf(e - m) * inv;
        const float* hr = g_h + (long long)s * HDIM;
        #pragma unroll
        for (int cidx = 0; cidx < HDIM / 32; cidx++)
            acc[cidx] += al * hr[lane + 32 * cidx];
    }

    const float* fr = new_weight + (long long)(1 + w) * HDIM;
    float* outr = g_ne + (long long)w * HDIM;
    #pragma unroll
    for (int cidx = 0; cidx < HDIM / 32; cidx++) {
        int col = lane + 32 * cidx;
        outr[col] = fr[col] + acc[cidx];
    }
}

// ---------------- final gather: soft prompt + embedding lookup ----------------
__global__ void k_gather(const void* __restrict__ x,
                         const float* __restrict__ ow,
                         const float* __restrict__ nw,
                         const float* __restrict__ soft,
                         float* __restrict__ out) {
    int w = (blockIdx.x * blockDim.x + threadIdx.x) >> 5;
    int lane = threadIdx.x & 31;
    if (w >= BATCH * SEQ) return;
    int b = w / SEQ, s = w % SEQ;

    const float* srcrow;
    if (s < N_SOFT) {
        srcrow = soft + (long long)s * HDIM;
    } else {
        long long idx = ldidx(x, (long long)b * SEQ + s, g_x64);
        if (idx < V_SIZE)                 srcrow = ow + idx * HDIM;
        else if (idx < V_SIZE + N_NODES)  srcrow = g_ne + (idx - V_SIZE) * HDIM;
        else                              srcrow = nw + (long long)(NEW_ROWS - 1) * HDIM;
    }
    const float4* s4 = (const float4*)srcrow;
    float4* o4 = (float4*)(out + (long long)w * HDIM);
    #pragma unroll
    for (int j = 0; j < HDIM / 128; j++)
        o4[lane + 32 * j] = s4[lane + 32 * j];
}

// ---------------- launch ----------------
extern "C" void kernel_launch(void* const* d_in, const int* in_sizes, int n_in,
                              void* d_out, int out_size) {
    const void*  x    = d_in[0];
    const void*  ei   = d_in[1];
    const float* ow   = (const float*)d_in[2];
    const float* nw   = (const float*)d_in[3];
    const float* soft = (const float*)d_in[4];
    const float* Wg   = (const float*)d_in[5];
    const float* asrc = (const float*)d_in[6];
    const float* adst = (const float*)d_in[7];
    float* out = (float*)d_out;

    static bool attr_set = false;
    if (!attr_set) {
        cudaFuncSetAttribute(k_gemm, cudaFuncAttributeMaxDynamicSharedMemorySize,
                             GEMM_SMEM_BYTES);
        attr_set = true;
    }

    k_init<<<(N_NODES + 1023) / 1024, 1024>>>((const unsigned*)x, (const unsigned*)ei);

    dim3 ggrid((N_NODES + BM - 1) / BM, HDIM / BN);
    k_gemm<<<ggrid, 256, GEMM_SMEM_BYTES>>>(nw + HDIM, Wg, asrc, adst);

    k_hist<<<(N_EDGES + 1023) / 1024, 1024>>>(ei);
    k_scan<<<1, 1024>>>();
    k_scatter<<<(N_EDGES + 1023) / 1024, 1024>>>(ei);

    k_gat<<<(N_NODES * 32 + 255) / 256, 256>>>(nw);

    k_gather<<<(BATCH * SEQ * 32 + 255) / 256, 256>>>(x, ow, nw, soft, out);
}

// round 3
// speedup vs baseline: 1.1461x; 1.0388x over previous
#include <cuda_runtime.h>
#include <cstdint>

// Problem constants
#define V_SIZE   30522
#define HDIM     768
#define BATCH    64
#define SEQ      512
#define NEW_ROWS 10004
#define N_NODES  10002
#define N_SOFT   8
#define N_EDGES  50000
#define LEAKY    0.2f

// ---------------- scratch (static device arrays; no allocations) ----------------
__device__ __align__(128) float g_h[N_NODES * HDIM];    // h = feat @ W_gat
__device__ __align__(128) float g_ne[N_NODES * HDIM];   // feat + agg
__device__ float g_ssrc[N_NODES];
__device__ float g_sdst[N_NODES];
__device__ int   g_cnt[N_NODES];
__device__ int   g_rowstart[N_NODES + 1];
__device__ int   g_cursor[N_NODES];
__device__ int   g_esrc[N_EDGES];
__device__ int   g_x64;
__device__ int   g_e64;

// ---------------- helpers ----------------
__device__ __forceinline__ long long ldidx(const void* p, long long i, int is64) {
    if (is64) return ((const long long*)p)[i];
    return (long long)(((const int*)p)[i]);
}

__device__ __forceinline__ void cpa16(uint32_t saddr, const void* gaddr, bool pred) {
    if (pred)
        asm volatile("cp.async.cg.shared.global [%0], [%1], 16;\n" :: "r"(saddr), "l"(gaddr));
    else
        asm volatile("cp.async.cg.shared.global [%0], [%1], 16, 0;\n" :: "r"(saddr), "l"(gaddr));
}

// ---------------- init: zero counters/score arrays + dtype detect ----------------
__global__ void k_init(const unsigned* x, const unsigned* ei) {
    int i = blockIdx.x * blockDim.x + threadIdx.x;
    if (i < N_NODES) { g_cnt[i] = 0; g_ssrc[i] = 0.f; g_sdst[i] = 0.f; }
    if (i == 0) {
        unsigned a = 0, b = 0;
        #pragma unroll
        for (int j = 0; j < 8; j++) { a |= x[2 * j + 1]; b |= ei[2 * j + 1]; }
        g_x64 = (a == 0) ? 1 : 0;
        g_e64 = (b == 0) ? 1 : 0;
    }
}

// ---------------- GEMM: g_h = A[10002,768] * W[768,768], TF32 MMA, 3-stage cp.async ----------------
#define BM 128
#define BN 128
#define BKK 32
#define AS_STRIDE 36
#define BS_STRIDE 136
#define STAGE_FLOATS (BM * AS_STRIDE + BKK * BS_STRIDE)
#define NSTAGE 3
#define GEMM_SMEM_BYTES (NSTAGE * STAGE_FLOATS * 4)

extern __shared__ float dynsmem[];

__global__ __launch_bounds__(256) void k_gemm(const float* __restrict__ Aw,
                                              const float* __restrict__ W,
                                              const float* __restrict__ asrc,
                                              const float* __restrict__ adst) {
    const int tid  = threadIdx.x;
    const int warp = tid >> 5, lane = tid & 31;
    const int wm = warp >> 1, wn = warp & 1;       // warp grid 4 (M) x 2 (N)
    const int g = lane >> 2, t = lane & 3;
    const int m0 = blockIdx.x * BM;
    const int n0 = blockIdx.y * BN;

    float c[2][8][4];
    #pragma unroll
    for (int mm = 0; mm < 2; mm++)
        #pragma unroll
        for (int nn = 0; nn < 8; nn++)
            #pragma unroll
            for (int q = 0; q < 4; q++) c[mm][nn][q] = 0.0f;

    const int NT = HDIM / BKK;   // 24

    auto load_tile = [&](int kt, int stage) {
        float* As = dynsmem + stage * STAGE_FLOATS;
        float* Bs = As + BM * AS_STRIDE;
        #pragma unroll
        for (int i = 0; i < 4; i++) {
            int idx = tid + i * 256;
            // A chunk
            int r  = idx >> 3;
            int c4 = (idx & 7) * 4;
            int grow = m0 + r;
            bool ok = grow < N_NODES;
            const float* gp = Aw + (long long)(ok ? grow : 0) * HDIM + kt + c4;
            uint32_t sa = (uint32_t)__cvta_generic_to_shared(As + r * AS_STRIDE + c4);
            cpa16(sa, gp, ok);
            // B chunk
            int k  = idx >> 5;
            int n4 = (idx & 31) * 4;
            const float* gq = W + (long long)(kt + k) * HDIM + n0 + n4;
            uint32_t sb = (uint32_t)__cvta_generic_to_shared(Bs + k * BS_STRIDE + n4);
            cpa16(sb, gq, true);
        }
    };

    load_tile(0, 0);
    asm volatile("cp.async.commit_group;\n");
    load_tile(BKK, 1);
    asm volatile("cp.async.commit_group;\n");

    for (int kt = 0; kt < NT; kt++) {
        if (kt + 2 < NT) {
            int st = kt + 2;
            load_tile(st * BKK, st % NSTAGE);
            asm volatile("cp.async.commit_group;\n");
            asm volatile("cp.async.wait_group 2;\n");
        } else if (kt + 1 < NT) {
            asm volatile("cp.async.wait_group 1;\n");
        } else {
            asm volatile("cp.async.wait_group 0;\n");
        }
        __syncthreads();

        const float* As = dynsmem + (kt % NSTAGE) * STAGE_FLOATS;
        const float* Bs = As + BM * AS_STRIDE;

        #pragma unroll
        for (int ks = 0; ks < 4; ks++) {
            const int kb = ks * 8;
            unsigned a[2][4], b2[8][2];
            #pragma unroll
            for (int mm = 0; mm < 2; mm++) {
                int rb = wm * 32 + mm * 16;
                a[mm][0] = __float_as_uint(As[(rb + g) * AS_STRIDE + kb + t]);
                a[mm][1] = __float_as_uint(As[(rb + 8 + g) * AS_STRIDE + kb + t]);
                a[mm][2] = __float_as_uint(As[(rb + g) * AS_STRIDE + kb + t + 4]);
                a[mm][3] = __float_as_uint(As[(rb + 8 + g) * AS_STRIDE + kb + t + 4]);
            }
            #pragma unroll
            for (int nn = 0; nn < 8; nn++) {
                int col = wn * 64 + nn * 8 + g;
                b2[nn][0] = __float_as_uint(Bs[(kb + t) * BS_STRIDE + col]);
                b2[nn][1] = __float_as_uint(Bs[(kb + t + 4) * BS_STRIDE + col]);
            }
            #pragma unroll
            for (int mm = 0; mm < 2; mm++)
                #pragma unroll
                for (int nn = 0; nn < 8; nn++) {
                    asm volatile(
                        "mma.sync.aligned.m16n8k8.row.col.f32.tf32.tf32.f32 "
                        "{%0,%1,%2,%3},{%4,%5,%6,%7},{%8,%9},{%0,%1,%2,%3};"
                        : "+f"(c[mm][nn][0]), "+f"(c[mm][nn][1]),
                          "+f"(c[mm][nn][2]), "+f"(c[mm][nn][3])
                        : "r"(a[mm][0]), "r"(a[mm][1]), "r"(a[mm][2]), "r"(a[mm][3]),
                          "r"(b2[nn][0]), "r"(b2[nn][1]));
                }
        }
        __syncthreads();
    }

    // Epilogue: store h + fused partial dots with a_src/a_dst
    #pragma unroll
    for (int mm = 0; mm < 2; mm++) {
        int row = m0 + wm * 32 + mm * 16 + g;
        float s1a = 0.f, s1b = 0.f, s2a = 0.f, s2b = 0.f;
        #pragma unroll
        for (int nn = 0; nn < 8; nn++) {
            int col = n0 + wn * 64 + nn * 8 + t * 2;
            float w0s = asrc[col], w1s = asrc[col + 1];
            float w0d = adst[col], w1d = adst[col + 1];
            s1a += c[mm][nn][0] * w0s + c[mm][nn][1] * w1s;
            s2a += c[mm][nn][0] * w0d + c[mm][nn][1] * w1d;
            s1b += c[mm][nn][2] * w0s + c[mm][nn][3] * w1s;
            s2b += c[mm][nn][2] * w0d + c[mm][nn][3] * w1d;
            if (row < N_NODES) {
                float2 v0 = make_float2(c[mm][nn][0], c[mm][nn][1]);
                *(float2*)(g_h + (long long)row * HDIM + col) = v0;
            }
            if (row + 8 < N_NODES) {
                float2 v1 = make_float2(c[mm][nn][2], c[mm][nn][3]);
                *(float2*)(g_h + (long long)(row + 8) * HDIM + col) = v1;
            }
        }
        #pragma unroll
        for (int off = 1; off < 4; off <<= 1) {
            s1a += __shfl_xor_sync(0xffffffffu, s1a, off);
            s2a += __shfl_xor_sync(0xffffffffu, s2a, off);
            s1b += __shfl_xor_sync(0xffffffffu, s1b, off);
            s2b += __shfl_xor_sync(0xffffffffu, s2b, off);
        }
        if (t == 0) {
            if (row < N_NODES) {
                atomicAdd(&g_ssrc[row], s1a);
                atomicAdd(&g_sdst[row], s2a);
            }
            if (row + 8 < N_NODES) {
                atomicAdd(&g_ssrc[row + 8], s1b);
                atomicAdd(&g_sdst[row + 8], s2b);
            }
        }
    }
}

// ---------------- CSR build: histogram -> scan -> scatter ----------------
__global__ void k_hist(const void* ei) {
    int e = blockIdx.x * blockDim.x + threadIdx.x;
    if (e < N_EDGES) {
        int dst = (int)ldidx(ei, (long long)N_EDGES + e, g_e64);
        atomicAdd(&g_cnt[dst], 1);
    }
}

#define SCAN_NPT 10   // 1024 * 10 = 10240 >= 10002

__global__ __launch_bounds__(1024) void k_scan() {
    __shared__ int sv[N_NODES];
    __shared__ int wsum[32];
    int tid = threadIdx.x;
    int lane = tid & 31, warp = tid >> 5;

    // coalesced staging load
    for (int i = tid; i < N_NODES; i += 1024) sv[i] = g_cnt[i];
    __syncthreads();

    int base = tid * SCAN_NPT;
    int local[SCAN_NPT];
    int tot = 0;
    #pragma unroll
    for (int j = 0; j < SCAN_NPT; j++) {
        int i = base + j;
        int v = (i < N_NODES) ? sv[i] : 0;
        local[j] = tot;          // exclusive within thread
        tot += v;
    }

    // block exclusive scan of per-thread totals
    int s = tot;
    #pragma unroll
    for (int off = 1; off < 32; off <<= 1) {
        int tv = __shfl_up_sync(0xffffffffu, s, off);
        if (lane >= off) s += tv;
    }
    if (lane == 31) wsum[warp] = s;
    __syncthreads();
    if (warp == 0) {
        int w = wsum[lane];
        #pragma unroll
        for (int off = 1; off < 32; off <<= 1) {
            int tv = __shfl_up_sync(0xffffffffu, w, off);
            if (lane >= off) w += tv;
        }
        wsum[lane] = w;
    }
    __syncthreads();
    int offset = ((warp > 0) ? wsum[warp - 1] : 0) + s - tot;  // thread-exclusive prefix

    #pragma unroll
    for (int j = 0; j < SCAN_NPT; j++) {
        int i = base + j;
        if (i < N_NODES) {
            int e = offset + local[j];
            g_rowstart[i] = e;
            g_cursor[i]   = e;
        }
    }
    if (tid == 1023) g_rowstart[N_NODES] = offset + tot;
}

__global__ void k_scatter(const void* ei) {
    int e = blockIdx.x * blockDim.x + threadIdx.x;
    if (e < N_EDGES) {
        int src = (int)ldidx(ei, e, g_e64);
        int dst = (int)ldidx(ei, (long long)N_EDGES + e, g_e64);
        int pos = atomicAdd(&g_cursor[dst], 1);
        g_esrc[pos] = src;
    }
}

// ---------------- per-dst softmax + aggregate (pull), write feat + agg ----------------
__global__ void k_gat(const float* __restrict__ new_weight) {
    int w = (blockIdx.x * blockDim.x + threadIdx.x) >> 5;
    int lane = threadIdx.x & 31;
    if (w >= N_NODES) return;

    int start = g_rowstart[w];
    int end   = g_rowstart[w + 1];
    float sd = g_sdst[w];

    float m = -INFINITY;
    for (int i = start + lane; i < end; i += 32) {
        float e = g_ssrc[g_esrc[i]] + sd;
        e = (e >= 0.f) ? e : LEAKY * e;
        m = fmaxf(m, e);
    }
    #pragma unroll
    for (int o = 16; o; o >>= 1) m = fmaxf(m, __shfl_xor_sync(0xffffffffu, m, o));

    float den = 0.f;
    if (end > start) {
        for (int i = start + lane; i < end; i += 32) {
            float e = g_ssrc[g_esrc[i]] + sd;
            e = (e >= 0.f) ? e : LEAKY * e;
            den += expf(e - m);
        }
        #pragma unroll
        for (int o = 16; o; o >>= 1) den += __shfl_xor_sync(0xffffffffu, den, o);
    }

    float acc[HDIM / 32];
    #pragma unroll
    for (int cidx = 0; cidx < HDIM / 32; cidx++) acc[cidx] = 0.f;

    float inv = 1.0f / (den + 1e-16f);
    for (int i = start; i < end; i++) {
        int s = g_esrc[i];
        float e = g_ssrc[s] + sd;
        e = (e >= 0.f) ? e : LEAKY * e;
        float al = expf(e - m) * inv;
        const float* hr = g_h + (long long)s * HDIM;
        #pragma unroll
        for (int cidx = 0; cidx < HDIM / 32; cidx++)
            acc[cidx] += al * hr[lane + 32 * cidx];
    }

    const float* fr = new_weight + (long long)(1 + w) * HDIM;
    float* outr = g_ne + (long long)w * HDIM;
    #pragma unroll
    for (int cidx = 0; cidx < HDIM / 32; cidx++) {
        int col = lane + 32 * cidx;
        outr[col] = fr[col] + acc[cidx];
    }
}

// ---------------- final gather: soft prompt + embedding lookup ----------------
__global__ void k_gather(const void* __restrict__ x,
                         const float* __restrict__ ow,
                         const float* __restrict__ nw,
                         const float* __restrict__ soft,
                         float* __restrict__ out) {
    int w = (blockIdx.x * blockDim.x + threadIdx.x) >> 5;
    int lane = threadIdx.x & 31;
    if (w >= BATCH * SEQ) return;
    int b = w / SEQ, s = w % SEQ;

    const float* srcrow;
    if (s < N_SOFT) {
        srcrow = soft + (long long)s * HDIM;
    } else {
        long long idx = ldidx(x, (long long)b * SEQ + s, g_x64);
        if (idx < V_SIZE)                 srcrow = ow + idx * HDIM;
        else if (idx < V_SIZE + N_NODES)  srcrow = g_ne + (idx - V_SIZE) * HDIM;
        else                              srcrow = nw + (long long)(NEW_ROWS - 1) * HDIM;
    }
    const float4* s4 = (const float4*)srcrow;
    float4* o4 = (float4*)(out + (long long)w * HDIM);
    #pragma unroll
    for (int j = 0; j < HDIM / 128; j++)
        o4[lane + 32 * j] = s4[lane + 32 * j];
}

// ---------------- launch ----------------
extern "C" void kernel_launch(void* const* d_in, const int* in_sizes, int n_in,
                              void* d_out, int out_size) {
    const void*  x    = d_in[0];
    const void*  ei   = d_in[1];
    const float* ow   = (const float*)d_in[2];
    const float* nw   = (const float*)d_in[3];
    const float* soft = (const float*)d_in[4];
    const float* Wg   = (const float*)d_in[5];
    const float* asrc = (const float*)d_in[6];
    const float* adst = (const float*)d_in[7];
    float* out = (float*)d_out;

    static bool attr_set = false;
    if (!attr_set) {
        cudaFuncSetAttribute(k_gemm, cudaFuncAttributeMaxDynamicSharedMemorySize,
                             GEMM_SMEM_BYTES);
        attr_set = true;
    }

    k_init<<<(N_NODES + 1023) / 1024, 1024>>>((const unsigned*)x, (const unsigned*)ei);

    dim3 ggrid((N_NODES + BM - 1) / BM, HDIM / BN);
    k_gemm<<<ggrid, 256, GEMM_SMEM_BYTES>>>(nw + HDIM, Wg, asrc, adst);

    k_hist<<<(N_EDGES + 1023) / 1024, 1024>>>(ei);
    k_scan<<<1, 1024>>>();
    k_scatter<<<(N_EDGES + 1023) / 1024, 1024>>>(ei);

    k_gat<<<(N_NODES * 32 + 255) / 256, 256>>>(nw);

    k_gather<<<(BATCH * SEQ * 32 + 255) / 256, 256>>>(x, ow, nw, soft, out);
}

// round 4
// speedup vs baseline: 1.3054x; 1.1390x over previous
#include <cuda_runtime.h>
#include <cstdint>

// Problem constants
#define V_SIZE   30522
#define HDIM     768
#define BATCH    64
#define SEQ      512
#define NEW_ROWS 10004
#define N_NODES  10002
#define N_SOFT   8
#define N_EDGES  50000
#define LEAKY    0.2f

// ---------------- scratch (static device arrays; no allocations) ----------------
__device__ __align__(128) float g_h[N_NODES * HDIM];    // h = feat @ W_gat
__device__ __align__(128) float g_ne[N_NODES * HDIM];   // feat + agg
__device__ float g_ssrc[N_NODES];
__device__ float g_sdst[N_NODES];
__device__ int   g_cnt[N_NODES];
__device__ int   g_rowstart[N_NODES + 1];
__device__ int   g_cursor[N_NODES];
__device__ int   g_esrc[N_EDGES];
__device__ int   g_x64;
__device__ int   g_e64;

// ---------------- helpers ----------------
__device__ __forceinline__ long long ldidx(const void* p, long long i, int is64) {
    if (is64) return ((const long long*)p)[i];
    return (long long)(((const int*)p)[i]);
}

__device__ __forceinline__ void cpa16(uint32_t saddr, const void* gaddr, bool pred) {
    if (pred)
        asm volatile("cp.async.cg.shared.global [%0], [%1], 16;\n" :: "r"(saddr), "l"(gaddr));
    else
        asm volatile("cp.async.cg.shared.global [%0], [%1], 16, 0;\n" :: "r"(saddr), "l"(gaddr));
}

// ---------------- init: zero counters/score arrays + dtype detect ----------------
__global__ void k_init(const unsigned* x, const unsigned* ei) {
    int i = blockIdx.x * blockDim.x + threadIdx.x;
    if (i < N_NODES) { g_cnt[i] = 0; g_ssrc[i] = 0.f; g_sdst[i] = 0.f; }
    if (i == 0) {
        unsigned a = 0, b = 0;
        #pragma unroll
        for (int j = 0; j < 8; j++) { a |= x[2 * j + 1]; b |= ei[2 * j + 1]; }
        g_x64 = (a == 0) ? 1 : 0;
        g_e64 = (b == 0) ? 1 : 0;
    }
}

// ---------------- GEMM: g_h = A[10002,768] * W[768,768], TF32 MMA, 3-stage cp.async ----------------
#define BM 128
#define BN 128
#define BKK 32
#define AS_STRIDE 36
#define BS_STRIDE 136
#define STAGE_FLOATS (BM * AS_STRIDE + BKK * BS_STRIDE)
#define NSTAGE 3
#define GEMM_SMEM_BYTES (NSTAGE * STAGE_FLOATS * 4)

extern __shared__ float dynsmem[];

__global__ __launch_bounds__(256) void k_gemm(const float* __restrict__ Aw,
                                              const float* __restrict__ W,
                                              const float* __restrict__ asrc,
                                              const float* __restrict__ adst) {
    const int tid  = threadIdx.x;
    const int warp = tid >> 5, lane = tid & 31;
    const int wm = warp >> 1, wn = warp & 1;
    const int g = lane >> 2, t = lane & 3;
    const int m0 = blockIdx.x * BM;
    const int n0 = blockIdx.y * BN;

    float c[2][8][4];
    #pragma unroll
    for (int mm = 0; mm < 2; mm++)
        #pragma unroll
        for (int nn = 0; nn < 8; nn++)
            #pragma unroll
            for (int q = 0; q < 4; q++) c[mm][nn][q] = 0.0f;

    const int NT = HDIM / BKK;   // 24

    auto load_tile = [&](int kt, int stage) {
        float* As = dynsmem + stage * STAGE_FLOATS;
        float* Bs = As + BM * AS_STRIDE;
        #pragma unroll
        for (int i = 0; i < 4; i++) {
            int idx = tid + i * 256;
            int r  = idx >> 3;
            int c4 = (idx & 7) * 4;
            int grow = m0 + r;
            bool ok = grow < N_NODES;
            const float* gp = Aw + (long long)(ok ? grow : 0) * HDIM + kt + c4;
            uint32_t sa = (uint32_t)__cvta_generic_to_shared(As + r * AS_STRIDE + c4);
            cpa16(sa, gp, ok);
            int k  = idx >> 5;
            int n4 = (idx & 31) * 4;
            const float* gq = W + (long long)(kt + k) * HDIM + n0 + n4;
            uint32_t sb = (uint32_t)__cvta_generic_to_shared(Bs + k * BS_STRIDE + n4);
            cpa16(sb, gq, true);
        }
    };

    load_tile(0, 0);
    asm volatile("cp.async.commit_group;\n");
    load_tile(BKK, 1);
    asm volatile("cp.async.commit_group;\n");

    for (int kt = 0; kt < NT; kt++) {
        if (kt + 2 < NT) {
            int st = kt + 2;
            load_tile(st * BKK, st % NSTAGE);
            asm volatile("cp.async.commit_group;\n");
            asm volatile("cp.async.wait_group 2;\n");
        } else if (kt + 1 < NT) {
            asm volatile("cp.async.wait_group 1;\n");
        } else {
            asm volatile("cp.async.wait_group 0;\n");
        }
        __syncthreads();

        const float* As = dynsmem + (kt % NSTAGE) * STAGE_FLOATS;
        const float* Bs = As + BM * AS_STRIDE;

        #pragma unroll
        for (int ks = 0; ks < 4; ks++) {
            const int kb = ks * 8;
            unsigned a[2][4], b2[8][2];
            #pragma unroll
            for (int mm = 0; mm < 2; mm++) {
                int rb = wm * 32 + mm * 16;
                a[mm][0] = __float_as_uint(As[(rb + g) * AS_STRIDE + kb + t]);
                a[mm][1] = __float_as_uint(As[(rb + 8 + g) * AS_STRIDE + kb + t]);
                a[mm][2] = __float_as_uint(As[(rb + g) * AS_STRIDE + kb + t + 4]);
                a[mm][3] = __float_as_uint(As[(rb + 8 + g) * AS_STRIDE + kb + t + 4]);
            }
            #pragma unroll
            for (int nn = 0; nn < 8; nn++) {
                int col = wn * 64 + nn * 8 + g;
                b2[nn][0] = __float_as_uint(Bs[(kb + t) * BS_STRIDE + col]);
                b2[nn][1] = __float_as_uint(Bs[(kb + t + 4) * BS_STRIDE + col]);
            }
            #pragma unroll
            for (int mm = 0; mm < 2; mm++)
                #pragma unroll
                for (int nn = 0; nn < 8; nn++) {
                    asm volatile(
                        "mma.sync.aligned.m16n8k8.row.col.f32.tf32.tf32.f32 "
                        "{%0,%1,%2,%3},{%4,%5,%6,%7},{%8,%9},{%0,%1,%2,%3};"
                        : "+f"(c[mm][nn][0]), "+f"(c[mm][nn][1]),
                          "+f"(c[mm][nn][2]), "+f"(c[mm][nn][3])
                        : "r"(a[mm][0]), "r"(a[mm][1]), "r"(a[mm][2]), "r"(a[mm][3]),
                          "r"(b2[nn][0]), "r"(b2[nn][1]));
                }
        }
        __syncthreads();
    }

    // Epilogue: store h + fused partial dots with a_src/a_dst
    #pragma unroll
    for (int mm = 0; mm < 2; mm++) {
        int row = m0 + wm * 32 + mm * 16 + g;
        float s1a = 0.f, s1b = 0.f, s2a = 0.f, s2b = 0.f;
        #pragma unroll
        for (int nn = 0; nn < 8; nn++) {
            int col = n0 + wn * 64 + nn * 8 + t * 2;
            float w0s = asrc[col], w1s = asrc[col + 1];
            float w0d = adst[col], w1d = adst[col + 1];
            s1a += c[mm][nn][0] * w0s + c[mm][nn][1] * w1s;
            s2a += c[mm][nn][0] * w0d + c[mm][nn][1] * w1d;
            s1b += c[mm][nn][2] * w0s + c[mm][nn][3] * w1s;
            s2b += c[mm][nn][2] * w0d + c[mm][nn][3] * w1d;
            if (row < N_NODES) {
                float2 v0 = make_float2(c[mm][nn][0], c[mm][nn][1]);
                *(float2*)(g_h + (long long)row * HDIM + col) = v0;
            }
            if (row + 8 < N_NODES) {
                float2 v1 = make_float2(c[mm][nn][2], c[mm][nn][3]);
                *(float2*)(g_h + (long long)(row + 8) * HDIM + col) = v1;
            }
        }
        #pragma unroll
        for (int off = 1; off < 4; off <<= 1) {
            s1a += __shfl_xor_sync(0xffffffffu, s1a, off);
            s2a += __shfl_xor_sync(0xffffffffu, s2a, off);
            s1b += __shfl_xor_sync(0xffffffffu, s1b, off);
            s2b += __shfl_xor_sync(0xffffffffu, s2b, off);
        }
        if (t == 0) {
            if (row < N_NODES) {
                atomicAdd(&g_ssrc[row], s1a);
                atomicAdd(&g_sdst[row], s2a);
            }
            if (row + 8 < N_NODES) {
                atomicAdd(&g_ssrc[row + 8], s1b);
                atomicAdd(&g_sdst[row + 8], s2b);
            }
        }
    }
}

// ---------------- CSR build: histogram -> scan -> scatter ----------------
__global__ void k_hist(const void* ei) {
    int e = blockIdx.x * blockDim.x + threadIdx.x;
    if (e < N_EDGES) {
        int dst = (int)ldidx(ei, (long long)N_EDGES + e, g_e64);
        atomicAdd(&g_cnt[dst], 1);
    }
}

#define SCAN_NPT 10   // 1024 * 10 = 10240 >= 10002

__global__ __launch_bounds__(1024) void k_scan() {
    __shared__ int sv[N_NODES + 1];
    __shared__ int wsum[32];
    int tid = threadIdx.x;
    int lane = tid & 31, warp = tid >> 5;

    for (int i = tid; i < N_NODES; i += 1024) sv[i] = g_cnt[i];
    __syncthreads();

    int base = tid * SCAN_NPT;
    int local[SCAN_NPT];
    int tot = 0;
    #pragma unroll
    for (int j = 0; j < SCAN_NPT; j++) {
        int i = base + j;
        int v = (i < N_NODES) ? sv[i] : 0;
        local[j] = tot;
        tot += v;
    }

    int s = tot;
    #pragma unroll
    for (int off = 1; off < 32; off <<= 1) {
        int tv = __shfl_up_sync(0xffffffffu, s, off);
        if (lane >= off) s += tv;
    }
    if (lane == 31) wsum[warp] = s;
    __syncthreads();
    if (warp == 0) {
        int w = wsum[lane];
        #pragma unroll
        for (int off = 1; off < 32; off <<= 1) {
            int tv = __shfl_up_sync(0xffffffffu, w, off);
            if (lane >= off) w += tv;
        }
        wsum[lane] = w;
    }
    __syncthreads();
    int offset = ((warp > 0) ? wsum[warp - 1] : 0) + s - tot;

    // write prefix back to smem (fast), then coalesced global write-out
    #pragma unroll
    for (int j = 0; j < SCAN_NPT; j++) {
        int i = base + j;
        if (i < N_NODES) sv[i] = offset + local[j];
    }
    if (tid == 1023) sv[N_NODES] = offset + tot;
    __syncthreads();
    for (int i = tid; i <= N_NODES; i += 1024) {
        int v = sv[i];
        g_rowstart[i] = v;
        if (i < N_NODES) g_cursor[i] = v;
    }
}

__global__ void k_scatter(const void* ei) {
    int e = blockIdx.x * blockDim.x + threadIdx.x;
    if (e < N_EDGES) {
        int src = (int)ldidx(ei, e, g_e64);
        int dst = (int)ldidx(ei, (long long)N_EDGES + e, g_e64);
        int pos = atomicAdd(&g_cursor[dst], 1);
        g_esrc[pos] = src;
    }
}

// ---------------- per-dst softmax + aggregate (pull), write feat + agg ----------------
__global__ void k_gat(const float* __restrict__ new_weight) {
    int w = (blockIdx.x * blockDim.x + threadIdx.x) >> 5;
    int lane = threadIdx.x & 31;
    if (w >= N_NODES) return;

    int start = g_rowstart[w];
    int end   = g_rowstart[w + 1];
    float sd = g_sdst[w];

    float m = -INFINITY;
    for (int i = start + lane; i < end; i += 32) {
        float e = g_ssrc[g_esrc[i]] + sd;
        e = (e >= 0.f) ? e : LEAKY * e;
        m = fmaxf(m, e);
    }
    #pragma unroll
    for (int o = 16; o; o >>= 1) m = fmaxf(m, __shfl_xor_sync(0xffffffffu, m, o));

    float den = 0.f;
    if (end > start) {
        for (int i = start + lane; i < end; i += 32) {
            float e = g_ssrc[g_esrc[i]] + sd;
            e = (e >= 0.f) ? e : LEAKY * e;
            den += expf(e - m);
        }
        #pragma unroll
        for (int o = 16; o; o >>= 1) den += __shfl_xor_sync(0xffffffffu, den, o);
    }

    float acc[HDIM / 32];
    #pragma unroll
    for (int cidx = 0; cidx < HDIM / 32; cidx++) acc[cidx] = 0.f;

    float inv = 1.0f / (den + 1e-16f);
    for (int i = start; i < end; i++) {
        int s = g_esrc[i];
        float e = g_ssrc[s] + sd;
        e = (e >= 0.f) ? e : LEAKY * e;
        float al = expf(e - m) * inv;
        const float* hr = g_h + (long long)s * HDIM;
        #pragma unroll
        for (int cidx = 0; cidx < HDIM / 32; cidx++)
            acc[cidx] += al * hr[lane + 32 * cidx];
    }

    const float* fr = new_weight + (long long)(1 + w) * HDIM;
    float* outr = g_ne + (long long)w * HDIM;
    #pragma unroll
    for (int cidx = 0; cidx < HDIM / 32; cidx++) {
        int col = lane + 32 * cidx;
        outr[col] = fr[col] + acc[cidx];
    }
}

// ---------------- gather (static rows): soft prompt + original vocab + tail ----------------
__global__ void k_gather_static(const void* __restrict__ x,
                                const float* __restrict__ ow,
                                const float* __restrict__ nw,
                                const float* __restrict__ soft,
                                float* __restrict__ out) {
    int w = (blockIdx.x * blockDim.x + threadIdx.x) >> 5;
    int lane = threadIdx.x & 31;
    if (w >= BATCH * SEQ) return;
    int b = w / SEQ, s = w % SEQ;

    const float* srcrow;
    if (s < N_SOFT) {
        srcrow = soft + (long long)s * HDIM;
    } else {
        long long idx = ldidx(x, (long long)b * SEQ + s, g_x64);
        if (idx < V_SIZE)                      srcrow = ow + idx * HDIM;
        else if (idx >= V_SIZE + N_NODES)      srcrow = nw + (long long)(NEW_ROWS - 1) * HDIM;
        else return;  // dynamic row handled by k_gather_dyn
    }
    const float4* s4 = (const float4*)srcrow;
    float4* o4 = (float4*)(out + (long long)w * HDIM);
    #pragma unroll
    for (int j = 0; j < HDIM / 128; j++)
        o4[lane + 32 * j] = s4[lane + 32 * j];
}

// ---------------- gather (dynamic rows): GAT-updated node embeddings ----------------
__global__ void k_gather_dyn(const void* __restrict__ x,
                             float* __restrict__ out) {
    int w = (blockIdx.x * blockDim.x + threadIdx.x) >> 5;
    int lane = threadIdx.x & 31;
    if (w >= BATCH * SEQ) return;
    int b = w / SEQ, s = w % SEQ;
    if (s < N_SOFT) return;

    long long idx = ldidx(x, (long long)b * SEQ + s, g_x64);
    if (idx < V_SIZE || idx >= V_SIZE + N_NODES) return;

    const float4* s4 = (const float4*)(g_ne + (idx - V_SIZE) * HDIM);
    float4* o4 = (float4*)(out + (long long)w * HDIM);
    #pragma unroll
    for (int j = 0; j < HDIM / 128; j++)
        o4[lane + 32 * j] = s4[lane + 32 * j];
}

// ---------------- launch ----------------
extern "C" void kernel_launch(void* const* d_in, const int* in_sizes, int n_in,
                              void* d_out, int out_size) {
    const void*  x    = d_in[0];
    const void*  ei   = d_in[1];
    const float* ow   = (const float*)d_in[2];
    const float* nw   = (const float*)d_in[3];
    const float* soft = (const float*)d_in[4];
    const float* Wg   = (const float*)d_in[5];
    const float* asrc = (const float*)d_in[6];
    const float* adst = (const float*)d_in[7];
    float* out = (float*)d_out;

    // One-time setup on the first (uncaptured correctness) call.
    static cudaStream_t s_csr = nullptr, s_emb = nullptr;
    static cudaEvent_t  e_init = nullptr, e_csr = nullptr, e_emb = nullptr;
    if (!s_csr) {
        cudaFuncSetAttribute(k_gemm, cudaFuncAttributeMaxDynamicSharedMemorySize,
                             GEMM_SMEM_BYTES);
        cudaStreamCreateWithFlags(&s_csr, cudaStreamNonBlocking);
        cudaStreamCreateWithFlags(&s_emb, cudaStreamNonBlocking);
        cudaEventCreateWithFlags(&e_init, cudaEventDisableTiming);
        cudaEventCreateWithFlags(&e_csr,  cudaEventDisableTiming);
        cudaEventCreateWithFlags(&e_emb,  cudaEventDisableTiming);
    }

    // main stream (0): init
    k_init<<<(N_NODES + 1023) / 1024, 1024>>>((const unsigned*)x, (const unsigned*)ei);
    cudaEventRecord(e_init, 0);

    // CSR chain on s_csr (needs g_e64 + zeroed g_cnt from init)
    cudaStreamWaitEvent(s_csr, e_init, 0);
    k_hist<<<(N_EDGES + 1023) / 1024, 1024, 0, s_csr>>>(ei);
    k_scan<<<1, 1024, 0, s_csr>>>();
    k_scatter<<<(N_EDGES + 1023) / 1024, 1024, 0, s_csr>>>(ei);
    cudaEventRecord(e_csr, s_csr);

    // static gather on s_emb (needs only g_x64 from init)
    cudaStreamWaitEvent(s_emb, e_init, 0);
    k_gather_static<<<(BATCH * SEQ * 32 + 255) / 256, 256, 0, s_emb>>>(x, ow, nw, soft, out);
    cudaEventRecord(e_emb, s_emb);

    // main stream: GEMM (overlaps CSR + static gather)
    dim3 ggrid((N_NODES + BM - 1) / BM, HDIM / BN);
    k_gemm<<<ggrid, 256, GEMM_SMEM_BYTES>>>(nw + HDIM, Wg, asrc, adst);

    // join CSR, run GAT, then dynamic gather; join static gather at the end
    cudaStreamWaitEvent(0, e_csr, 0);
    k_gat<<<(N_NODES * 32 + 255) / 256, 256>>>(nw);
    cudaStreamWaitEvent(0, e_emb, 0);
    k_gather_dyn<<<(BATCH * SEQ * 32 + 255) / 256, 256>>>(x, out);
}

// round 6
// speedup vs baseline: 1.5891x; 1.2173x over previous
#include <cuda_runtime.h>
#include <cstdint>

// Problem constants
#define V_SIZE   30522
#define HDIM     768
#define BATCH    64
#define SEQ      512
#define NEW_ROWS 10004
#define N_NODES  10002
#define N_SOFT   8
#define N_EDGES  50000
#define LEAKY    0.2f

// ---------------- scratch (static device arrays; no allocations) ----------------
__device__ __align__(128) float g_af[N_NODES * HDIM];   // compacted aggfeat rows
__device__ __align__(128) float g_ne[N_NODES * HDIM];   // compacted output node rows
__device__ float g_wsrc[HDIM];
__device__ float g_wdst[HDIM];
__device__ float g_ssrc[N_NODES];
__device__ float g_sdst[N_NODES];
__device__ int   g_cnt[N_NODES];
__device__ int   g_rowstart[N_NODES + 1];
__device__ int   g_cursor[N_NODES];
__device__ int   g_esrc[N_EDGES];
__device__ int   g_nf[N_NODES];      // needed flags
__device__ int   g_slot[N_NODES];    // node -> compacted slot
__device__ int   g_sel[N_NODES];     // slot -> node
__device__ int   g_nsel;
__device__ int   g_x64;
__device__ int   g_e64;

// ---------------- helpers ----------------
__device__ __forceinline__ long long ldidx(const void* p, long long i, int is64) {
    if (is64) return ((const long long*)p)[i];
    return (long long)(((const int*)p)[i]);
}

__device__ __forceinline__ void cpa16(uint32_t saddr, const void* gaddr, bool pred) {
    if (pred)
        asm volatile("cp.async.cg.shared.global [%0], [%1], 16;\n" :: "r"(saddr), "l"(gaddr));
    else
        asm volatile("cp.async.cg.shared.global [%0], [%1], 16, 0;\n" :: "r"(saddr), "l"(gaddr));
}

// ---------------- init: zero counters/flags + dtype detect ----------------
__global__ void k_init(const unsigned* x, const unsigned* ei) {
    int i = blockIdx.x * blockDim.x + threadIdx.x;
    if (i < N_NODES) { g_cnt[i] = 0; g_nf[i] = 0; }
    if (i == 0) {
        unsigned a = 0, b = 0;
        #pragma unroll
        for (int j = 0; j < 8; j++) { a |= x[2 * j + 1]; b |= ei[2 * j + 1]; }
        g_x64 = (a == 0) ? 1 : 0;
        g_e64 = (b == 0) ? 1 : 0;
    }
}

// ---------------- w vectors: w_src = W @ a_src, w_dst = W @ a_dst (fp32) ----------------
__global__ void k_wvec(const float* __restrict__ W,
                       const float* __restrict__ asrc,
                       const float* __restrict__ adst) {
    int k = (blockIdx.x * blockDim.x + threadIdx.x) >> 5;  // row of W
    int lane = threadIdx.x & 31;
    if (k >= HDIM) return;
    const float* wr = W + (long long)k * HDIM;
    float s1 = 0.f, s2 = 0.f;
    #pragma unroll
    for (int j = 0; j < HDIM / 32; j++) {
        int col = lane + 32 * j;
        float v = wr[col];
        s1 += v * asrc[col];
        s2 += v * adst[col];
    }
    #pragma unroll
    for (int o = 16; o; o >>= 1) {
        s1 += __shfl_xor_sync(0xffffffffu, s1, o);
        s2 += __shfl_xor_sync(0xffffffffu, s2, o);
    }
    if (lane == 0) { g_wsrc[k] = s1; g_wdst[k] = s2; }
}

// ---------------- s_src/s_dst = feat . w_src / w_dst ----------------
__global__ void k_sdots(const float* __restrict__ nw) {
    int w = (blockIdx.x * blockDim.x + threadIdx.x) >> 5;
    int lane = threadIdx.x & 31;
    if (w >= N_NODES) return;
    const float* fr = nw + (long long)(1 + w) * HDIM;
    float s1 = 0.f, s2 = 0.f;
    #pragma unroll
    for (int j = 0; j < HDIM / 32; j++) {
        int col = lane + 32 * j;
        float v = fr[col];
        s1 += v * g_wsrc[col];
        s2 += v * g_wdst[col];
    }
    #pragma unroll
    for (int o = 16; o; o >>= 1) {
        s1 += __shfl_xor_sync(0xffffffffu, s1, o);
        s2 += __shfl_xor_sync(0xffffffffu, s2, o);
    }
    if (lane == 0) { g_ssrc[w] = s1; g_sdst[w] = s2; }
}

// ---------------- flags: mark nodes referenced by x ----------------
__global__ void k_flags(const void* __restrict__ x) {
    int i = blockIdx.x * blockDim.x + threadIdx.x;
    if (i >= BATCH * SEQ) return;
    int s = i % SEQ;
    if (s < N_SOFT) return;
    long long idx = ldidx(x, i, g_x64);
    if (idx >= V_SIZE && idx < V_SIZE + N_NODES) g_nf[idx - V_SIZE] = 1;
}

// ---------------- compaction scan: g_nf -> g_slot (exclusive), g_sel, g_nsel ----------------
#define SCAN_NPT 10

__global__ __launch_bounds__(1024) void k_cscan() {
    __shared__ int sv[N_NODES];
    __shared__ int wsum[32];
    int tid = threadIdx.x;
    int lane = tid & 31, warp = tid >> 5;

    for (int i = tid; i < N_NODES; i += 1024) sv[i] = g_nf[i];
    __syncthreads();

    int base = tid * SCAN_NPT;
    int local[SCAN_NPT];
    int tot = 0;
    #pragma unroll
    for (int j = 0; j < SCAN_NPT; j++) {
        int i = base + j;
        int v = (i < N_NODES) ? sv[i] : 0;
        local[j] = tot;
        tot += v;
    }
    int s = tot;
    #pragma unroll
    for (int off = 1; off < 32; off <<= 1) {
        int tv = __shfl_up_sync(0xffffffffu, s, off);
        if (lane >= off) s += tv;
    }
    if (lane == 31) wsum[warp] = s;
    __syncthreads();
    if (warp == 0) {
        int w = wsum[lane];
        #pragma unroll
        for (int off = 1; off < 32; off <<= 1) {
            int tv = __shfl_up_sync(0xffffffffu, w, off);
            if (lane >= off) w += tv;
        }
        wsum[lane] = w;
    }
    __syncthreads();
    int offset = ((warp > 0) ? wsum[warp - 1] : 0) + s - tot;

    #pragma unroll
    for (int j = 0; j < SCAN_NPT; j++) {
        int i = base + j;
        if (i < N_NODES) {
            int p = offset + local[j];
            g_slot[i] = p;
            if (sv[i]) g_sel[p] = i;
        }
    }
    if (tid == 1023) g_nsel = offset + tot;
}

// ---------------- CSR build: histogram -> scan -> scatter ----------------
__global__ void k_hist(const void* ei) {
    int e = blockIdx.x * blockDim.x + threadIdx.x;
    if (e < N_EDGES) {
        int dst = (int)ldidx(ei, (long long)N_EDGES + e, g_e64);
        atomicAdd(&g_cnt[dst], 1);
    }
}

__global__ __launch_bounds__(1024) void k_scan() {
    __shared__ int sv[N_NODES + 1];
    __shared__ int wsum[32];
    int tid = threadIdx.x;
    int lane = tid & 31, warp = tid >> 5;

    for (int i = tid; i < N_NODES; i += 1024) sv[i] = g_cnt[i];
    __syncthreads();

    int base = tid * SCAN_NPT;
    int local[SCAN_NPT];
    int tot = 0;
    #pragma unroll
    for (int j = 0; j < SCAN_NPT; j++) {
        int i = base + j;
        int v = (i < N_NODES) ? sv[i] : 0;
        local[j] = tot;
        tot += v;
    }
    int s = tot;
    #pragma unroll
    for (int off = 1; off < 32; off <<= 1) {
        int tv = __shfl_up_sync(0xffffffffu, s, off);
        if (lane >= off) s += tv;
    }
    if (lane == 31) wsum[warp] = s;
    __syncthreads();
    if (warp == 0) {
        int w = wsum[lane];
        #pragma unroll
        for (int off = 1; off < 32; off <<= 1) {
            int tv = __shfl_up_sync(0xffffffffu, w, off);
            if (lane >= off) w += tv;
        }
        wsum[lane] = w;
    }
    __syncthreads();
    int offset = ((warp > 0) ? wsum[warp - 1] : 0) + s - tot;

    #pragma unroll
    for (int j = 0; j < SCAN_NPT; j++) {
        int i = base + j;
        if (i < N_NODES) sv[i] = offset + local[j];
    }
    if (tid == 1023) sv[N_NODES] = offset + tot;
    __syncthreads();
    for (int i = tid; i <= N_NODES; i += 1024) {
        int v = sv[i];
        g_rowstart[i] = v;
        if (i < N_NODES) g_cursor[i] = v;
    }
}

__global__ void k_scatter(const void* ei) {
    int e = blockIdx.x * blockDim.x + threadIdx.x;
    if (e < N_EDGES) {
        int src = (int)ldidx(ei, e, g_e64);
        int dst = (int)ldidx(ei, (long long)N_EDGES + e, g_e64);
        int pos = atomicAdd(&g_cursor[dst], 1);
        g_esrc[pos] = src;
    }
}

// ---------------- per-needed-dst softmax + feat-space aggregation ----------------
__global__ void k_gat(const float* __restrict__ nw) {
    int w = (blockIdx.x * blockDim.x + threadIdx.x) >> 5;
    int lane = threadIdx.x & 31;
    if (w >= N_NODES) return;
    if (!g_nf[w]) return;

    int start = g_rowstart[w];
    int end   = g_rowstart[w + 1];
    float sd = g_sdst[w];
    int slot = g_slot[w];

    float m = -INFINITY;
    for (int i = start + lane; i < end; i += 32) {
        float e = g_ssrc[g_esrc[i]] + sd;
        e = (e >= 0.f) ? e : LEAKY * e;
        m = fmaxf(m, e);
    }
    #pragma unroll
    for (int o = 16; o; o >>= 1) m = fmaxf(m, __shfl_xor_sync(0xffffffffu, m, o));

    float den = 0.f;
    if (end > start) {
        for (int i = start + lane; i < end; i += 32) {
            float e = g_ssrc[g_esrc[i]] + sd;
            e = (e >= 0.f) ? e : LEAKY * e;
            den += expf(e - m);
        }
        #pragma unroll
        for (int o = 16; o; o >>= 1) den += __shfl_xor_sync(0xffffffffu, den, o);
    }

    float acc[HDIM / 32];
    #pragma unroll
    for (int cidx = 0; cidx < HDIM / 32; cidx++) acc[cidx] = 0.f;

    float inv = 1.0f / (den + 1e-16f);
    for (int i = start; i < end; i++) {
        int s = g_esrc[i];
        float e = g_ssrc[s] + sd;
        e = (e >= 0.f) ? e : LEAKY * e;
        float al = expf(e - m) * inv;
        const float* fr = nw + (long long)(1 + s) * HDIM;   // feat[src]
        #pragma unroll
        for (int cidx = 0; cidx < HDIM / 32; cidx++)
            acc[cidx] += al * fr[lane + 32 * cidx];
    }

    float* outr = g_af + (long long)slot * HDIM;
    #pragma unroll
    for (int cidx = 0; cidx < HDIM / 32; cidx++)
        outr[lane + 32 * cidx] = acc[cidx];
}

// ---------------- GEMM2: g_ne[slot] = feat[sel[slot]] + g_af[slot] @ W  (TF32 MMA) ----------------
#define BM 128
#define BN 128
#define BKK 32
#define AS_STRIDE 36
#define BS_STRIDE 136
#define STAGE_FLOATS (BM * AS_STRIDE + BKK * BS_STRIDE)
#define NSTAGE 3
#define GEMM_SMEM_BYTES (NSTAGE * STAGE_FLOATS * 4)

extern __shared__ float dynsmem[];

__global__ __launch_bounds__(256) void k_gemm(const float* __restrict__ W,
                                              const float* __restrict__ nw) {
    const int nsel = g_nsel;
    const int m0 = blockIdx.x * BM;
    if (m0 >= nsel) return;
    const int n0 = blockIdx.y * BN;

    const int tid  = threadIdx.x;
    const int warp = tid >> 5, lane = tid & 31;
    const int wm = warp >> 1, wn = warp & 1;
    const int g = lane >> 2, t = lane & 3;

    float c[2][8][4];
    #pragma unroll
    for (int mm = 0; mm < 2; mm++)
        #pragma unroll
        for (int nn = 0; nn < 8; nn++)
            #pragma unroll
            for (int q = 0; q < 4; q++) c[mm][nn][q] = 0.0f;

    const int NT = HDIM / BKK;   // 24

    auto load_tile = [&](int kt, int stage) {
        float* As = dynsmem + stage * STAGE_FLOATS;
        float* Bs = As + BM * AS_STRIDE;
        #pragma unroll
        for (int i = 0; i < 4; i++) {
            int idx = tid + i * 256;
            int r  = idx >> 3;
            int c4 = (idx & 7) * 4;
            int grow = m0 + r;
            bool ok = grow < nsel;
            const float* gp = g_af + (long long)(ok ? grow : 0) * HDIM + kt + c4;
            uint32_t sa = (uint32_t)__cvta_generic_to_shared(As + r * AS_STRIDE + c4);
            cpa16(sa, gp, ok);
            int k  = idx >> 5;
            int n4 = (idx & 31) * 4;
            const float* gq = W + (long long)(kt + k) * HDIM + n0 + n4;
            uint32_t sb = (uint32_t)__cvta_generic_to_shared(Bs + k * BS_STRIDE + n4);
            cpa16(sb, gq, true);
        }
    };

    load_tile(0, 0);
    asm volatile("cp.async.commit_group;\n");
    load_tile(BKK, 1);
    asm volatile("cp.async.commit_group;\n");

    for (int kt = 0; kt < NT; kt++) {
        if (kt + 2 < NT) {
            int st = kt + 2;
            load_tile(st * BKK, st % NSTAGE);
            asm volatile("cp.async.commit_group;\n");
            asm volatile("cp.async.wait_group 2;\n");
        } else if (kt + 1 < NT) {
            asm volatile("cp.async.wait_group 1;\n");
        } else {
            asm volatile("cp.async.wait_group 0;\n");
        }
        __syncthreads();

        const float* As = dynsmem + (kt % NSTAGE) * STAGE_FLOATS;
        const float* Bs = As + BM * AS_STRIDE;

        #pragma unroll
        for (int ks = 0; ks < 4; ks++) {
            const int kb = ks * 8;
            unsigned a[2][4], b2[8][2];
            #pragma unroll
            for (int mm = 0; mm < 2; mm++) {
                int rb = wm * 32 + mm * 16;
                a[mm][0] = __float_as_uint(As[(rb + g) * AS_STRIDE + kb + t]);
                a[mm][1] = __float_as_uint(As[(rb + 8 + g) * AS_STRIDE + kb + t]);
                a[mm][2] = __float_as_uint(As[(rb + g) * AS_STRIDE + kb + t + 4]);
                a[mm][3] = __float_as_uint(As[(rb + 8 + g) * AS_STRIDE + kb + t + 4]);
            }
            #pragma unroll
            for (int nn = 0; nn < 8; nn++) {
                int col = wn * 64 + nn * 8 + g;
                b2[nn][0] = __float_as_uint(Bs[(kb + t) * BS_STRIDE + col]);
                b2[nn][1] = __float_as_uint(Bs[(kb + t + 4) * BS_STRIDE + col]);
            }
            #pragma unroll
            for (int mm = 0; mm < 2; mm++)
                #pragma unroll
                for (int nn = 0; nn < 8; nn++) {
                    asm volatile(
                        "mma.sync.aligned.m16n8k8.row.col.f32.tf32.tf32.f32 "
                        "{%0,%1,%2,%3},{%4,%5,%6,%7},{%8,%9},{%0,%1,%2,%3};"
                        : "+f"(c[mm][nn][0]), "+f"(c[mm][nn][1]),
                          "+f"(c[mm][nn][2]), "+f"(c[mm][nn][3])
                        : "r"(a[mm][0]), "r"(a[mm][1]), "r"(a[mm][2]), "r"(a[mm][3]),
                          "r"(b2[nn][0]), "r"(b2[nn][1]));
                }
        }
        __syncthreads();
    }

    // Epilogue: g_ne[row] = c + feat[sel[row]]
    #pragma unroll
    for (int mm = 0; mm < 2; mm++) {
        int row = m0 + wm * 32 + mm * 16 + g;
        int nodeA = (row < nsel) ? g_sel[row] : 0;
        int nodeB = (row + 8 < nsel) ? g_sel[row + 8] : 0;
        const float* fA = nw + (long long)(1 + nodeA) * HDIM;
        const float* fB = nw + (long long)(1 + nodeB) * HDIM;
        #pragma unroll
        for (int nn = 0; nn < 8; nn++) {
            int col = n0 + wn * 64 + nn * 8 + t * 2;
            if (row < nsel) {
                float2 fv = *(const float2*)(fA + col);
                float2 v0 = make_float2(c[mm][nn][0] + fv.x, c[mm][nn][1] + fv.y);
                *(float2*)(g_ne + (long long)row * HDIM + col) = v0;
            }
            if (row + 8 < nsel) {
                float2 fv = *(const float2*)(fB + col);
                float2 v1 = make_float2(c[mm][nn][2] + fv.x, c[mm][nn][3] + fv.y);
                *(float2*)(g_ne + (long long)(row + 8) * HDIM + col) = v1;
            }
        }
    }
}

// ---------------- gather (static rows): soft prompt + original vocab + tail ----------------
__global__ void k_gather_static(const void* __restrict__ x,
                                const float* __restrict__ ow,
                                const float* __restrict__ nw,
                                const float* __restrict__ soft,
                                float* __restrict__ out) {
    int w = (blockIdx.x * blockDim.x + threadIdx.x) >> 5;
    int lane = threadIdx.x & 31;
    if (w >= BATCH * SEQ) return;
    int b = w / SEQ, s = w % SEQ;

    const float* srcrow;
    if (s < N_SOFT) {
        srcrow = soft + (long long)s * HDIM;
    } else {
        long long idx = ldidx(x, (long long)b * SEQ + s, g_x64);
        if (idx < V_SIZE)                      srcrow = ow + idx * HDIM;
        else if (idx >= V_SIZE + N_NODES)      srcrow = nw + (long long)(NEW_ROWS - 1) * HDIM;
        else return;
    }
    const float4* s4 = (const float4*)srcrow;
    float4* o4 = (float4*)(out + (long long)w * HDIM);
    #pragma unroll
    for (int j = 0; j < HDIM / 128; j++)
        o4[lane + 32 * j] = s4[lane + 32 * j];
}

// ---------------- gather (dynamic rows): compacted GAT-updated node embeddings ----------------
__global__ void k_gather_dyn(const void* __restrict__ x,
                             float* __restrict__ out) {
    int w = (blockIdx.x * blockDim.x + threadIdx.x) >> 5;
    int lane = threadIdx.x & 31;
    if (w >= BATCH * SEQ) return;
    int b = w / SEQ, s = w % SEQ;
    if (s < N_SOFT) return;

    long long idx = ldidx(x, (long long)b * SEQ + s, g_x64);
    if (idx < V_SIZE || idx >= V_SIZE + N_NODES) return;

    int slot = g_slot[idx - V_SIZE];
    const float4* s4 = (const float4*)(g_ne + (long long)slot * HDIM);
    float4* o4 = (float4*)(out + (long long)w * HDIM);
    #pragma unroll
    for (int j = 0; j < HDIM / 128; j++)
        o4[lane + 32 * j] = s4[lane + 32 * j];
}

// ---------------- launch ----------------
extern "C" void kernel_launch(void* const* d_in, const int* in_sizes, int n_in,
                              void* d_out, int out_size) {
    const void*  x    = d_in[0];
    const void*  ei   = d_in[1];
    const float* ow   = (const float*)d_in[2];
    const float* nw   = (const float*)d_in[3];
    const float* soft = (const float*)d_in[4];
    const float* Wg   = (const float*)d_in[5];
    const float* asrc = (const float*)d_in[6];
    const float* adst = (const float*)d_in[7];
    float* out = (float*)d_out;

    static cudaStream_t s_csr = nullptr, s_emb = nullptr, s_wv = nullptr;
    static cudaEvent_t  e_init = nullptr, e_csr = nullptr, e_emb = nullptr, e_sd = nullptr;
    if (!s_csr) {
        cudaFuncSetAttribute(k_gemm, cudaFuncAttributeMaxDynamicSharedMemorySize,
                             GEMM_SMEM_BYTES);
        cudaStreamCreateWithFlags(&s_csr, cudaStreamNonBlocking);
        cudaStreamCreateWithFlags(&s_emb, cudaStreamNonBlocking);
        cudaStreamCreateWithFlags(&s_wv,  cudaStreamNonBlocking);
        cudaEventCreateWithFlags(&e_init, cudaEventDisableTiming);
        cudaEventCreateWithFlags(&e_csr,  cudaEventDisableTiming);
        cudaEventCreateWithFlags(&e_emb,  cudaEventDisableTiming);
        cudaEventCreateWithFlags(&e_sd,   cudaEventDisableTiming);
    }

    // main stream: init (zero + dtype detect)
    k_init<<<(N_NODES + 1023) / 1024, 1024>>>((const unsigned*)x, (const unsigned*)ei);
    cudaEventRecord(e_init, 0);

    // s_wv: MUST fork from the capture-origin stream via an event before any launch
    cudaStreamWaitEvent(s_wv, e_init, 0);
    k_wvec<<<(HDIM * 32 + 255) / 256, 256, 0, s_wv>>>(Wg, asrc, adst);
    k_sdots<<<(N_NODES * 32 + 255) / 256, 256, 0, s_wv>>>(nw);
    cudaEventRecord(e_sd, s_wv);

    // s_csr: CSR chain
    cudaStreamWaitEvent(s_csr, e_init, 0);
    k_hist<<<(N_EDGES + 1023) / 1024, 1024, 0, s_csr>>>(ei);
    k_scan<<<1, 1024, 0, s_csr>>>();
    k_scatter<<<(N_EDGES + 1023) / 1024, 1024, 0, s_csr>>>(ei);
    cudaEventRecord(e_csr, s_csr);

    // s_emb: static gather
    cudaStreamWaitEvent(s_emb, e_init, 0);
    k_gather_static<<<(BATCH * SEQ * 32 + 255) / 256, 256, 0, s_emb>>>(x, ow, nw, soft, out);
    cudaEventRecord(e_emb, s_emb);

    // main stream: flags -> compaction scan
    k_flags<<<(BATCH * SEQ + 255) / 256, 256>>>(x);
    k_cscan<<<1, 1024>>>();

    // join CSR + sdots, run feat-space GAT aggregation
    cudaStreamWaitEvent(0, e_csr, 0);
    cudaStreamWaitEvent(0, e_sd, 0);
    k_gat<<<(N_NODES * 32 + 255) / 256, 256>>>(nw);

    // compacted GEMM (agg @ W + feat)
    dim3 ggrid((N_NODES + BM - 1) / BM, HDIM / BN);
    k_gemm<<<ggrid, 256, GEMM_SMEM_BYTES>>>(Wg, nw);

    // dynamic gather
    cudaStreamWaitEvent(0, e_emb, 0);
    k_gather_dyn<<<(BATCH * SEQ * 32 + 255) / 256, 256>>>(x, out);
}